// round 5
// baseline (speedup 1.0000x reference)
#include <cuda_runtime.h>
#include <cstdint>

#define NQ      8
#define NLAYERS 4
#define DIN     1024
#define DOUT    1024
#define BMAX    8192

using ull = unsigned long long;

// ---------------- packed f32x2 helpers (Blackwell dual-FP32) ----------------
__device__ __forceinline__ ull pk(float x, float y) {
    ull r; asm("mov.b64 %0,{%1,%2};" : "=l"(r) : "f"(x), "f"(y)); return r;
}
__device__ __forceinline__ void up2(ull a, float& x, float& y) {
    asm("mov.b64 {%0,%1},%2;" : "=f"(x), "=f"(y) : "l"(a));
}
__device__ __forceinline__ ull dup2(float x) { return pk(x, x); }
__device__ __forceinline__ ull fma2(ull a, ull b, ull c) {
    ull d; asm("fma.rn.f32x2 %0,%1,%2,%3;" : "=l"(d) : "l"(a), "l"(b), "l"(c)); return d;
}
__device__ __forceinline__ ull mul2(ull a, ull b) {
    ull d; asm("mul.rn.f32x2 %0,%1,%2;" : "=l"(d) : "l"(a), "l"(b)); return d;
}
__device__ __forceinline__ ull swp(ull a) { float x, y; up2(a, x, y); return pk(y, x); }
__device__ __forceinline__ ull shflx(ull a, int m) {
    float x, y; up2(a, x, y);
    x = __shfl_xor_sync(0xffffffffu, x, m);
    y = __shfl_xor_sync(0xffffffffu, y, m);
    return pk(x, y);
}

// ---------------- device buffers / gate coefficients ----------------
__device__ float  g_ucoef[NLAYERS * NQ * 8];
__device__ float2 g_cs[BMAX * NQ];   // (cos(h), sin(h)) per row per wire
__device__ float  g_ev[BMAX * NQ];   // <Z_i> per row

// ================= K1: angles = x @ Win^T + bin ; store (cos,sin) =========
// block=128 (4 warps), 4 rows/warp, 16 rows/block, grid = B/16 = 512 blocks.
__global__ __launch_bounds__(128)
void k1_angles(const float* __restrict__ x,
               const float* __restrict__ Win,
               const float* __restrict__ bin,
               const float* __restrict__ qw)
{
    const int lane = threadIdx.x & 31;
    const int warp = threadIdx.x >> 5;
    const int row0 = (blockIdx.x * 4 + warp) * 4;

    float acc[4][8];
#pragma unroll
    for (int r = 0; r < 4; r++)
#pragma unroll
        for (int q = 0; q < NQ; q++) acc[r][q] = 0.f;

    const float4* w4 = reinterpret_cast<const float4*>(Win);
    const float4* xr[4];
#pragma unroll
    for (int r = 0; r < 4; r++)
        xr[r] = reinterpret_cast<const float4*>(x + (size_t)(row0 + r) * DIN);

#pragma unroll
    for (int j = 0; j < 8; j++) {
        float4 xv[4];
#pragma unroll
        for (int r = 0; r < 4; r++)
            xv[r] = __ldcs(&xr[r][lane + 32 * j]);
#pragma unroll
        for (int q = 0; q < NQ; q++) {
            float4 wv = __ldg(&w4[q * 256 + lane + 32 * j]);
#pragma unroll
            for (int r = 0; r < 4; r++)
                acc[r][q] += xv[r].x * wv.x + xv[r].y * wv.y
                           + xv[r].z * wv.z + xv[r].w * wv.w;
        }
    }
    // full butterfly: every lane ends with every (r,q) sum
#pragma unroll
    for (int off = 16; off; off >>= 1)
#pragma unroll
        for (int r = 0; r < 4; r++)
#pragma unroll
            for (int q = 0; q < NQ; q++)
                acc[r][q] += __shfl_xor_sync(0xffffffffu, acc[r][q], off);

    // static predicated gather: lane o = r*8 + q takes acc[r][q]
    float h = acc[0][0];
#pragma unroll
    for (int r = 0; r < 4; r++)
#pragma unroll
        for (int q = 0; q < NQ; q++) {
            const int o = r * 8 + q;
            if (o != 0 && lane == o) h = acc[r][q];
        }

    const int rr = lane >> 3;
    const int qq = lane & 7;
    float c, s;
    __sincosf(0.5f * (h + __ldg(&bin[qq])), &s, &c);
    g_cs[(size_t)(row0 + rr) * NQ + qq] = make_float2(c, s);

    // gate-coefficient prep (one warp of block 0)
    if (blockIdx.x == 0 && threadIdx.x < NLAYERS * NQ) {
        int t = threadIdx.x;
        int l = t >> 3, i = t & 7;
        float th = qw[l * 16 + i];        // weights[l][0][i] (RX)
        float ph = qw[l * 16 + 8 + i];    // weights[l][1][i] (RZ)
        float s2, c2, sp, cp;
        sincosf(0.5f * th, &s2, &c2);
        sincosf(0.5f * ph, &sp, &cp);
        float* u = &g_ucoef[t * 8];
        u[0] =  c2 * cp;  u[1] = -c2 * sp;   // u00
        u[2] = -s2 * sp;  u[3] = -s2 * cp;   // u01
        u[4] =  s2 * sp;  u[5] = -s2 * cp;   // u10
        u[6] =  c2 * cp;  u[7] =  c2 * sp;   // u11
    }
}

// ================= K2: quantum circuit, frame-tracked (no CNOT data movement)
// One warp per row. Physical amp p = lane*8 + r; packed f32x2 pairs over r-bit0:
// reg j holds (r=2j, r=2j+1). Physical bits 7..3 = lane bits 4..0, bits 2..0 = r.
// Gate on logical wire t in frame F: pair mask M = F^{-1} e_t, parity row R.
template<int M, int R>
__device__ __forceinline__ void apply_gate(ull* Ar, ull* Ai,
                                           float4 ua, float4 ub, int lane)
{
    constexpr int lm    = M >> 3;        // lane shuffle mask
    constexpr int loj   = (M & 7) >> 1;  // packed-register xor
    constexpr int lo0   = M & 1;         // crosses packed pair -> swp
    constexpr int Rlane = R >> 3;
    constexpr int Rj    = (R & 7) >> 1;
    constexpr int R0    = R & 1;

    const bool pl = (__popc(lane & Rlane) & 1) != 0;

    ull o_r[4], o_i[4];
#pragma unroll
    for (int j = 0; j < 4; j++) { o_r[j] = Ar[j]; o_i[j] = Ai[j]; }

#pragma unroll
    for (int j = 0; j < 4; j++) {
        ull Pr = o_r[j ^ loj], Pi = o_i[j ^ loj];
        if (lo0) { Pr = swp(Pr); Pi = swp(Pi); }
        if (lm)  { Pr = shflx(Pr, lm); Pi = shflx(Pi, lm); }
        const bool b = pl ^ (((__popc(j & Rj)) & 1) != 0);
        ull dr, di, ndi, orr, oi, noi;
        if (R0 == 0) {
            float fdr = b ? ub.z : ua.x, fdi = b ? ub.w : ua.y;
            float foR = b ? ub.x : ua.z, foI = b ? ub.y : ua.w;
            dr = dup2(fdr); di = dup2(fdi); ndi = dup2(-fdi);
            orr = dup2(foR); oi = dup2(foI); noi = dup2(-foI);
        } else {
            dr  = b ? pk(ub.z,  ua.x)  : pk(ua.x,  ub.z);
            di  = b ? pk(ub.w,  ua.y)  : pk(ua.y,  ub.w);
            ndi = b ? pk(-ub.w, -ua.y) : pk(-ua.y, -ub.w);
            orr = b ? pk(ub.x,  ua.z)  : pk(ua.z,  ub.x);
            oi  = b ? pk(ub.y,  ua.w)  : pk(ua.w,  ub.y);
            noi = b ? pk(-ub.y, -ua.w) : pk(-ua.w, -ub.y);
        }
        Ar[j] = fma2(noi, Pi, fma2(orr, Pr, fma2(ndi, o_i[j], mul2(dr, o_r[j]))));
        Ai[j] = fma2(oi,  Pr, fma2(orr, Pi, fma2(di,  o_r[j], mul2(dr, o_i[j]))));
    }
}

__global__ __launch_bounds__(256)
void k2_circuit()
{
    const int lane = threadIdx.x & 31;
    const int warp = threadIdx.x >> 5;
    const int row  = blockIdx.x * 8 + warp;

    float C[NQ], S[NQ];
    {
        const float4* cs4 = reinterpret_cast<const float4*>(&g_cs[(size_t)row * NQ]);
#pragma unroll
        for (int j = 0; j < 4; j++) {
            float4 v = __ldg(&cs4[j]);
            C[2 * j] = v.x; S[2 * j] = v.y; C[2 * j + 1] = v.z; S[2 * j + 1] = v.w;
        }
    }

    // initial product state (identity frame)
    float ar[8], ai[8];
    {
        float prr = 1.f, pri = 0.f;
#pragma unroll
        for (int w = 0; w < 5; w++) {
            int b = (lane >> (4 - w)) & 1;
            float qr = b ? S[w] * S[w] : C[w] * C[w];
            float qi = -S[w] * C[w];
            float nr = prr * qr - pri * qi;
            pri = prr * qi + pri * qr;
            prr = nr;
        }
#pragma unroll
        for (int r = 0; r < 8; r++) {
            float lr = prr, li = pri;
#pragma unroll
            for (int w = 5; w < 8; w++) {
                int b = (r >> (7 - w)) & 1;
                float qr = b ? S[w] * S[w] : C[w] * C[w];
                float qi = -S[w] * C[w];
                float nr = lr * qr - li * qi;
                li = lr * qi + li * qr;
                lr = nr;
            }
            ar[r] = lr; ai[r] = li;
        }
    }
    ull Ar[4], Ai[4];
#pragma unroll
    for (int j = 0; j < 4; j++) {
        Ar[j] = pk(ar[2 * j], ar[2 * j + 1]);
        Ai[j] = pk(ai[2 * j], ai[2 * j + 1]);
    }

    const float4* u4 = reinterpret_cast<const float4*>(g_ucoef);
#define G(L, I, MM, RR) { float4 ua = __ldg(&u4[((L) * 8 + (I)) * 2]); \
                          float4 ub = __ldg(&u4[((L) * 8 + (I)) * 2 + 1]); \
                          apply_gate<MM, RR>(Ar, Ai, ua, ub, lane); }
    // layer 1 (identity frame)
    G(0,0,0x80,0x80) G(0,1,0x40,0x40) G(0,2,0x20,0x20) G(0,3,0x10,0x10)
    G(0,4,0x08,0x08) G(0,5,0x04,0x04) G(0,6,0x02,0x02) G(0,7,0x01,0x01)
    // layer 2 (after CNOT chain 1)
    G(1,0,0xC0,0x80) G(1,1,0x60,0xC0) G(1,2,0x30,0xE0) G(1,3,0x18,0xF0)
    G(1,4,0x0C,0xF8) G(1,5,0x06,0xFC) G(1,6,0x03,0xFE) G(1,7,0x01,0xFF)
    // layer 3
    G(2,0,0xA0,0x80) G(2,1,0x50,0x40) G(2,2,0x28,0xA0) G(2,3,0x14,0x50)
    G(2,4,0x0A,0xA8) G(2,5,0x05,0x54) G(2,6,0x02,0xAA) G(2,7,0x01,0x55)
    // layer 4
    G(3,0,0xF0,0x80) G(3,1,0x78,0xC0) G(3,2,0x3C,0x60) G(3,3,0x1E,0x30)
    G(3,4,0x0F,0x98) G(3,5,0x07,0xCC) G(3,6,0x03,0x66) G(3,7,0x01,0x33)
#undef G

    // probabilities
    ull P[4];
#pragma unroll
    for (int j = 0; j < 4; j++) P[j] = fma2(Ai[j], Ai[j], mul2(Ar[j], Ar[j]));
    float p[8];
#pragma unroll
    for (int j = 0; j < 4; j++) up2(P[j], p[2 * j], p[2 * j + 1]);

    float ptot = ((p[0] + p[1]) + (p[2] + p[3])) + ((p[4] + p[5]) + (p[6] + p[7]));

    // final sign rows Rf = [0x80,0x40,0x20,0x10,0x88,0x44,0x22,0x11]
    float s5 = ((p[0] + p[1]) + (p[2] + p[3])) - ((p[4] + p[5]) + (p[6] + p[7]));
    float s6 = ((p[0] + p[1]) - (p[2] + p[3])) + ((p[4] + p[5]) - (p[6] + p[7]));
    float s7 = ((p[0] - p[1]) + (p[2] - p[3])) + ((p[4] - p[5]) + (p[6] - p[7]));

    float ev[NQ];
    ev[0] = (__popc(lane & 0x10) & 1) ? -ptot : ptot;
    ev[1] = (__popc(lane & 0x08) & 1) ? -ptot : ptot;
    ev[2] = (__popc(lane & 0x04) & 1) ? -ptot : ptot;
    ev[3] = (__popc(lane & 0x02) & 1) ? -ptot : ptot;
    ev[4] = (__popc(lane & 0x11) & 1) ? -ptot : ptot;
    ev[5] = (__popc(lane & 0x08) & 1) ? -s5 : s5;
    ev[6] = (__popc(lane & 0x04) & 1) ? -s6 : s6;
    ev[7] = (__popc(lane & 0x02) & 1) ? -s7 : s7;

#pragma unroll
    for (int off = 16; off; off >>= 1)
#pragma unroll
        for (int i = 0; i < NQ; i++)
            ev[i] += __shfl_xor_sync(0xffffffffu, ev[i], off);

    // static predicated gather (avoid dynamic register indexing)
    float myev = ev[0];
#pragma unroll
    for (int i = 1; i < NQ; i++)
        if (lane == i) myev = ev[i];
    if (lane < NQ)
        g_ev[(size_t)row * NQ + lane] = myev;
}

// ================= K3: out = ev @ Wout^T + bout ===========================
// 1024 blocks x 256 threads; 8 rows/block; each thread owns 4 output cols.
__global__ __launch_bounds__(256)
void k3_out(const float* __restrict__ Wout,
            const float* __restrict__ bout,
            float* __restrict__ out)
{
    const int c0   = threadIdx.x * 4;
    const int row0 = blockIdx.x * 8;

    const float4* wo4 = reinterpret_cast<const float4*>(Wout);  // [DOUT][2]
    float4 wa[4], wb[4];
#pragma unroll
    for (int k = 0; k < 4; k++) {
        wa[k] = __ldg(&wo4[(c0 + k) * 2 + 0]);
        wb[k] = __ldg(&wo4[(c0 + k) * 2 + 1]);
    }
    float4 bo = __ldg(&reinterpret_cast<const float4*>(bout)[threadIdx.x]);

#pragma unroll
    for (int r = 0; r < 8; r++) {
        int row = row0 + r;
        const float4* e4 = reinterpret_cast<const float4*>(&g_ev[(size_t)row * NQ]);
        float4 ea = __ldg(e4 + 0);
        float4 eb = __ldg(e4 + 1);
        float4 o;
        o.x = bo.x + ea.x * wa[0].x + ea.y * wa[0].y + ea.z * wa[0].z + ea.w * wa[0].w
                   + eb.x * wb[0].x + eb.y * wb[0].y + eb.z * wb[0].z + eb.w * wb[0].w;
        o.y = bo.y + ea.x * wa[1].x + ea.y * wa[1].y + ea.z * wa[1].z + ea.w * wa[1].w
                   + eb.x * wb[1].x + eb.y * wb[1].y + eb.z * wb[1].z + eb.w * wb[1].w;
        o.z = bo.z + ea.x * wa[2].x + ea.y * wa[2].y + ea.z * wa[2].z + ea.w * wa[2].w
                   + eb.x * wb[2].x + eb.y * wb[2].y + eb.z * wb[2].z + eb.w * wb[2].w;
        o.w = bo.w + ea.x * wa[3].x + ea.y * wa[3].y + ea.z * wa[3].z + ea.w * wa[3].w
                   + eb.x * wb[3].x + eb.y * wb[3].y + eb.z * wb[3].z + eb.w * wb[3].w;
        reinterpret_cast<float4*>(out + (size_t)row * DOUT)[threadIdx.x] = o;
    }
}

extern "C" void kernel_launch(void* const* d_in, const int* in_sizes, int n_in,
                              void* d_out, int out_size) {
    const float* x    = (const float*)d_in[0];
    const float* Win  = (const float*)d_in[1];
    const float* bin  = (const float*)d_in[2];
    const float* qw   = (const float*)d_in[3];
    const float* Wout = (const float*)d_in[4];
    const float* bout = (const float*)d_in[5];
    float* out = (float*)d_out;

    int B = in_sizes[0] / DIN;            // 8192
    k1_angles<<<B / 16, 128>>>(x, Win, bin, qw);
    k2_circuit<<<B / 8, 256>>>();
    k3_out<<<B / 8, 256>>>(Wout, bout, out);
}